// round 16
// baseline (speedup 1.0000x reference)
#include <cuda_runtime.h>
#include <cuda_fp16.h>
#include <math.h>
#include <stdint.h>

#define WW    5
#define LL    20
#define ROWI  105      // W*(1+L)
#define CEc   32
#define OCc   30
#define Kc    3
#define WEc   50
#define HIDc  100
#define TAGSc 36
#define QN    128
#define FCIN  400      // (WE+OC)*W
#define WSTR  80       // WE+OC

#define NW 32
#define NT (NW*32)
#define NPAIR 16
#define ITP 8          // items per warp-pair

#define KTILES 10      // fc1 K padded 150 -> 160
#define NTILES 13      // fc1 N padded 100 -> 104
#define NFRAG  (KTILES*NTILES)   // 130

#define KT2 7          // out K padded 104 -> 112
#define NT2 5          // out N padded 36 -> 40
#define NFRAG2 (KT2*NT2)         // 35

#define NQ   (WW*QN*HIDc)        // 64000
#define NB_  (NFRAG*32)          // 4160
#define NB2_ (NFRAG2*32)         // 1120
#define NP   (100*OCc)           // 3000
#define QCB  80                  // Q-coop blocks: 5 w x 16 chunks of 8 ids

// ---- only remaining global table ----
__device__ float g_Q[NQ];            // [w][id][j]

__device__ __forceinline__ float tanh_ap(float x) {
    float y; asm("tanh.approx.f32 %0, %1;" : "=f"(y) : "f"(x)); return y;
}
__device__ __forceinline__ void mma16816(float& c0, float& c1, float& c2, float& c3,
        uint32_t a0, uint32_t a1, uint32_t a2, uint32_t a3, uint32_t b0, uint32_t b1) {
    asm volatile("mma.sync.aligned.m16n8k16.row.col.f32.f16.f16.f32 "
        "{%0,%1,%2,%3}, {%4,%5,%6,%7}, {%8,%9}, {%0,%1,%2,%3};"
        : "+f"(c0), "+f"(c1), "+f"(c2), "+f"(c3)
        : "r"(a0), "r"(a1), "r"(a2), "r"(a3), "r"(b0), "r"(b1));
}
__device__ __forceinline__ void pair_bar(int id) {
    asm volatile("bar.sync %0, %1;" :: "r"(id), "r"(64) : "memory");
}

// Q-only prep (cooperative, coalesced)
__global__ void prep_Q(const float* __restrict__ emb,
                       const float* __restrict__ fc1_w) {
    __shared__ float sF[HIDc*WEc];
    __shared__ float sE[8*WEc];
    const int tid = threadIdx.x;
    int w = blockIdx.x >> 4, chunk = blockIdx.x & 15;
    for (int i = tid; i < HIDc*WEc; i += 256) {
        int j = i / WEc, d = i % WEc;
        sF[i] = fc1_w[j*FCIN + w*WSTR + d];
    }
    int c0 = chunk*8;
    for (int i = tid; i < 8*WEc; i += 256)
        sE[i] = emb[(c0 + i/WEc)*WEc + (i % WEc)];
    __syncthreads();
    for (int o = tid; o < 8*HIDc; o += 256) {
        int cl = o / HIDc, j = o % HIDc;
        const float* e = &sE[cl*WEc];
        const float* f = &sF[j*WEc];
        float s = 0.f;
        #pragma unroll
        for (int d = 0; d < WEc; d++) s += e[d]*f[d];
        g_Q[(w*QN + c0 + cl)*HIDc + j] = s;
    }
}

// ---- smem layout (bytes) ----
#define OFFB_P4   0          // 25600  half [c][128] (256B/char)
#define OFFB_WB   25600      // 33280  fc1 B-frag table
#define OFFB_WB2  58880      // 8960   out B-frag table
#define OFFB_FB   67840      // 400
#define OFFB_OB   68240      // 160
#define OFFB_CB   68400      // 128
#define OFFB_WS   68528
// per-pair scratch: ids u16 [8*105] 1680->1696 | pool16 [8][160] 2560 | Qs f32 [8][104] 3328 | sH16 [8][112] 1792
#define PSB       9376
#define POOL_OFF  1696
#define QS_OFF    4256
#define SH_OFF    7584
#define SM_BYTES  (OFFB_WS + NPAIR*PSB + 1024)   // 219568 (+pad for benign OOB frag reads)

// fc1 mma over 8 A-rows, N-tiles [NT0, NT0+NTN)
template<int NT0, int NTN>
__device__ __forceinline__ void mma_fc1(const __half* pool16, const char* sWB,
                                        const float* Qs, __half* sH16, int lane) {
    const int lr = lane >> 2;
    const int lq = lane & 3;
    float C[NTN][4];
    #pragma unroll
    for (int t = 0; t < NTN; t++) { C[t][0]=0.f; C[t][1]=0.f; C[t][2]=0.f; C[t][3]=0.f; }
    #pragma unroll
    for (int kt = 0; kt < KTILES; kt++) {
        uint32_t a0 = *(const uint32_t*)&pool16[lr*160 + kt*16 + lq*2];
        uint32_t a2 = *(const uint32_t*)&pool16[lr*160 + kt*16 + lq*2 + 8];
        #pragma unroll
        for (int t = 0; t < NTN; t++) {
            uint2 b = *(const uint2*)(sWB + ((kt*NTILES + NT0 + t)*32 + lane)*8);
            mma16816(C[t][0], C[t][1], C[t][2], C[t][3], a0, a0, a2, a2, b.x, b.y);
        }
    }
    #pragma unroll
    for (int t = 0; t < NTN; t++) {
        int col = (NT0 + t)*8 + lq*2;
        float2 qv = *(const float2*)&Qs[lr*104 + col];
        __half2 hv = __floats2half2_rn(tanh_ap(C[t][0] + qv.x),
                                       tanh_ap(C[t][1] + qv.y));
        *(__half2*)&sH16[lr*112 + col] = hv;
    }
}

__global__ __launch_bounds__(NT) void pos_main(
    const int*   __restrict__ input,
    const float* __restrict__ emb,
    const float* __restrict__ conv_w,
    const float* __restrict__ char_emb,
    const float* __restrict__ conv_b,
    const float* __restrict__ fc1_w,
    const float* __restrict__ fc1_b,
    const float* __restrict__ out_w,
    const float* __restrict__ out_b,
    float*       __restrict__ out,
    int nb)
{
    extern __shared__ char smb[];
    const char* sWB  = smb + OFFB_WB;
    const char* sWB2 = smb + OFFB_WB2;
    float*  sFb  = (float*)(smb + OFFB_FB);
    float*  sOb  = (float*)(smb + OFFB_OB);
    float*  sCb  = (float*)(smb + OFFB_CB);

    const int tid = threadIdx.x;

    // ==== prologue: build ALL tables in-block from raw weights ====
    // P table (conv factored through char_emb), fp16, dual-copy k2 layout
    for (int i = tid; i < NP; i += NT) {
        int oc = i % OCc, c = i / OCc;
        float s0 = 0.f, s1 = 0.f, s2 = 0.f;
        #pragma unroll
        for (int ce = 0; ce < CEc; ce++) {
            float e = char_emb[c*CEc + ce];
            const float* w = &conv_w[(oc*CEc + ce)*Kc];
            s0 += w[0]*e; s1 += w[1]*e; s2 += w[2]*e;
        }
        int pr = oc >> 1, lo = oc & 1;
        __half* row = (__half*)(smb + OFFB_P4) + c*128;
        row[pr*4 + lo]      = __float2half_rn(s0);
        row[pr*4 + 2 + lo]  = __float2half_rn(s1);
        __half h2v = __float2half_rn(s2);
        row[64 + pr*2 + lo] = h2v;
        row[96 + pr*2 + lo] = h2v;
    }
    // fc1 pooled-part B fragments
    for (int i = tid; i < NB_; i += NT) {
        int lane = i & 31, tile = i >> 5;
        int kt = tile / NTILES, nt = tile % NTILES;
        int n = nt*8 + (lane >> 2);
        int kb = kt*16 + (lane & 3)*2;
        const int koff[4] = {0, 1, 8, 9};
        __half v[4];
        #pragma unroll
        for (int q = 0; q < 4; q++) {
            int k = kb + koff[q];
            float f = 0.f;
            if (k < WW*OCc && n < HIDc) {
                int w = k / OCc, oc = k % OCc;
                f = fc1_w[n*FCIN + w*WSTR + WEc + oc];
            }
            v[q] = __float2half_rn(f);
        }
        __half2 h01; h01.x = v[0]; h01.y = v[1];
        __half2 h23; h23.x = v[2]; h23.y = v[3];
        uint2 pk; pk.x = *(uint32_t*)&h01; pk.y = *(uint32_t*)&h23;
        *(uint2*)(smb + OFFB_WB + (size_t)i*8) = pk;
    }
    // out-layer B fragments
    for (int i = tid; i < NB2_; i += NT) {
        int lane = i & 31, tile = i >> 5;
        int kt = tile / NT2, nt = tile % NT2;
        int n = nt*8 + (lane >> 2);       // tag
        int kb = kt*16 + (lane & 3)*2;    // hidden j
        const int koff[4] = {0, 1, 8, 9};
        __half v[4];
        #pragma unroll
        for (int q = 0; q < 4; q++) {
            int k = kb + koff[q];
            float f = (k < HIDc && n < TAGSc) ? out_w[n*HIDc + k] : 0.f;
            v[q] = __float2half_rn(f);
        }
        __half2 h01; h01.x = v[0]; h01.y = v[1];
        __half2 h23; h23.x = v[2]; h23.y = v[3];
        uint2 pk; pk.x = *(uint32_t*)&h01; pk.y = *(uint32_t*)&h23;
        *(uint2*)(smb + OFFB_WB2 + (size_t)i*8) = pk;
    }
    if (tid < HIDc)  sFb[tid] = fc1_b[tid];
    if (tid < TAGSc) sOb[tid] = out_b[tid];
    if (tid < OCc)   sCb[tid] = conv_b[tid];
    __syncthreads();

    const int warp = tid >> 5, lane = tid & 31;
    const int pair = warp >> 1, sub = warp & 1;
    char* ws = smb + OFFB_WS + pair*PSB;
    unsigned short* sIds = (unsigned short*)ws;         // [8*105] u16
    __half* pool16 = (__half*)(ws + POOL_OFF);          // [8][160] fp16
    float*  Qs     = (float*)(ws + QS_OFF);             // [8][104] f32
    __half* sH16   = (__half*)(ws + SH_OFF);            // [8][112] fp16

    const int myb = sub*4;   // this warp owns items myb..myb+3

    // one-time pad zeroing (each warp its 4 rows)
    for (int i = lane; i < 40; i += 32)
        pool16[(myb + i/10)*160 + 150 + (i%10)] = __half(0.f);
    if (lane < 16)
        *(uint32_t*)&sH16[(myb + (lane >> 2))*112 + 104 + (lane & 3)*2] = 0u;

    // conv lane mapping: half-warp = item of pair, lane&15 = oc pair
    const int lp   = lane & 15;
    const int hw   = lane >> 4;
    const bool cact = (lp < 15);
    const char* Pk01 = smb + OFFB_P4 + lp*8;
    const char* Pk2  = smb + OFFB_P4 + 128 + hw*64 + lp*4;
    __half2 cbh = __floats2half2_rn(0.f, 0.f);
    if (cact) cbh = __floats2half2_rn(sCb[2*lp], sCb[2*lp+1]);

    const int j0 = lane*4;
    const int lr = lane >> 2, lq = lane & 3;
    const int ngroups = (nb + ITP - 1) / ITP;

    for (int group = blockIdx.x*NPAIR + pair; group < ngroups; group += gridDim.x*NPAIR) {
        const int base = group*ITP;
        const int nit = (nb - base < ITP) ? (nb - base) : ITP;
        int mynit = nit - myb; mynit = mynit < 0 ? 0 : (mynit > 4 ? 4 : mynit);

        // ids for my 4 items; char slots pre-scaled to row byte offsets (c*256)
        for (int i = lane; i < mynit*ROWI; i += 32) {
            int v = input[(base + myb)*ROWI + i];
            sIds[myb*ROWI + i] = (unsigned short)(((i % 21) == 0) ? v : (v << 8));
        }
        if (mynit < 4)
            for (int i = mynit*ROWI + lane; i < 4*ROWI; i += 32) sIds[myb*ROWI + i] = 0;
        __syncwarp();

        // -- conv + maxpool: 2 of my items/pass, half2 over oc pairs -> pool fp16 --
        if (cact) {
            #pragma unroll
            for (int ip = 0; ip < 2; ip++) {
                const int it = myb + ip*2 + hw;
                #pragma unroll 1
                for (int w = 0; w < WW; w++) {
                    const unsigned short* cc = &sIds[it*ROWI + w*21 + 1];
                    __half2 m  = __floats2half2_rn(-60000.f, -60000.f);
                    __half2 s1 = __floats2half2_rn(0.f, 0.f);
                    __half2 s0 = s1;
                    #pragma unroll
                    for (int p = 0; p < LL; p++) {
                        const int c = cc[p];
                        uint2    r01 = *(const uint2*)(Pk01 + c);
                        uint32_t r2v = *(const uint32_t*)(Pk2 + c);
                        __half2 v0 = *(const __half2*)&r01.x;
                        __half2 v1 = *(const __half2*)&r01.y;
                        __half2 v2 = *(const __half2*)&r2v;
                        if (p >= 2) m = __hmax2(m, __hadd2(s1, v2));
                        s1 = __hadd2(s0, v1);
                        s0 = v0;
                    }
                    *(__half2*)&pool16[it*160 + w*OCc + 2*lp] = __hadd2(m, cbh);
                }
            }
        }

        // -- Q phase for my 4 items --
        if (lane < 26) {
            for (int itl = 0; itl < 4; itl++) {
                const int it = myb + itl;
                float4 acc = {0.f, 0.f, 0.f, 0.f};
                if (lane < 25) {
                    if (itl < mynit) {
                        #pragma unroll
                        for (int w = 0; w < WW; w++) {
                            int id = sIds[it*ROWI + w*21];
                            if (id < QN) {
                                const float4 q = *(const float4*)&g_Q[(w*QN + id)*HIDc + j0];
                                acc.x += q.x; acc.y += q.y; acc.z += q.z; acc.w += q.w;
                            } else {   // exact fallback (never taken for this data)
                                const float* e = emb + (long)id*WEc;
                                #pragma unroll 1
                                for (int d = 0; d < WEc; d++) {
                                    float ev = e[d];
                                    acc.x += ev * fc1_w[(j0+0)*FCIN + w*WSTR + d];
                                    acc.y += ev * fc1_w[(j0+1)*FCIN + w*WSTR + d];
                                    acc.z += ev * fc1_w[(j0+2)*FCIN + w*WSTR + d];
                                    acc.w += ev * fc1_w[(j0+3)*FCIN + w*WSTR + d];
                                }
                            }
                        }
                    }
                    acc.x += sFb[j0+0]; acc.y += sFb[j0+1];
                    acc.z += sFb[j0+2]; acc.w += sFb[j0+3];
                }
                *(float4*)&Qs[it*104 + j0] = acc;
            }
        }

        pair_bar(pair);   // all 8 items' pool16 + Qs ready

        // -- fc1 on tensor cores, N-split across the warp pair --
        if (sub == 0) mma_fc1<0, 7>(pool16, sWB, Qs, sH16, lane);
        else          mma_fc1<7, 6>(pool16, sWB, Qs, sH16, lane);

        pair_bar(pair);   // sH16 complete

        // -- output layer on tensor cores, N-split: sub0 tiles 0-2, sub1 tiles 3-4 --
        {
            const int t0 = sub ? 3 : 0;
            const int tn = sub ? 2 : 3;
            float C[3][4];
            #pragma unroll
            for (int t = 0; t < 3; t++) { C[t][0]=0.f; C[t][1]=0.f; C[t][2]=0.f; C[t][3]=0.f; }
            #pragma unroll
            for (int kt = 0; kt < KT2; kt++) {
                uint32_t a0 = *(const uint32_t*)&sH16[lr*112 + kt*16 + lq*2];
                uint32_t a2 = *(const uint32_t*)&sH16[lr*112 + kt*16 + lq*2 + 8];
                #pragma unroll
                for (int t = 0; t < 3; t++) {
                    if (t < tn) {
                        uint2 b = *(const uint2*)(sWB2 + ((kt*NT2 + t0 + t)*32 + lane)*8);
                        mma16816(C[t][0], C[t][1], C[t][2], C[t][3], a0, a0, a2, a2, b.x, b.y);
                    }
                }
            }
            if (lr < nit) {
                float* orow = out + (long)(base + lr)*TAGSc;
                #pragma unroll
                for (int t = 0; t < 3; t++) {
                    if (t < tn) {
                        int c = (t0 + t)*8 + lq*2;
                        if (c < TAGSc)     orow[c]     = C[t][0] + sOb[c];
                        if (c + 1 < TAGSc) orow[c + 1] = C[t][1] + sOb[c + 1];
                    }
                }
            }
        }
        // next iteration's first pair_bar orders these reads before overwrite
    }
}

extern "C" void kernel_launch(void* const* d_in, const int* in_sizes, int n_in,
                              void* d_out, int out_size) {
    const int*   input = (const int*)  d_in[0];
    const float* emb   = (const float*)d_in[1];
    const float* cemb  = (const float*)d_in[2];
    const float* convw = (const float*)d_in[3];
    const float* convb = (const float*)d_in[4];
    const float* fc1w  = (const float*)d_in[5];
    const float* fc1b  = (const float*)d_in[6];
    const float* outw  = (const float*)d_in[7];
    const float* outb  = (const float*)d_in[8];
    float* out = (float*)d_out;

    int nb = in_sizes[0] / ROWI;

    cudaFuncSetAttribute(pos_main, cudaFuncAttributeMaxDynamicSharedMemorySize, SM_BYTES);

    prep_Q<<<QCB, 256>>>(emb, fc1w);

    pos_main<<<148, NT, SM_BYTES>>>(input, emb, convw, cemb, convb,
                                    fc1w, fc1b, outw, outb, out, nb);
}

// round 17
// speedup vs baseline: 3.1095x; 3.1095x over previous
#include <cuda_runtime.h>
#include <cuda_fp16.h>
#include <math.h>
#include <stdint.h>

#define WW    5
#define LL    20
#define ROWI  105      // W*(1+L)
#define CEc   32
#define OCc   30
#define Kc    3
#define WEc   50
#define HIDc  100
#define TAGSc 36
#define QN    128
#define FCIN  400      // (WE+OC)*W
#define WSTR  80       // WE+OC

#define NW 32
#define NT (NW*32)
#define NPAIR 16
#define ITP 8          // items per warp-pair

#define KTILES 10      // fc1 K padded 150 -> 160
#define NTILES 13      // fc1 N padded 100 -> 104
#define NFRAG  (KTILES*NTILES)   // 130

#define KT2 7          // out K padded 104 -> 112
#define NT2 5          // out N padded 36 -> 40
#define NFRAG2 (KT2*NT2)         // 35

#define NQ   (WW*QN*HIDc)        // 64000
#define NB_  (NFRAG*32)          // 4160
#define NB2_ (NFRAG2*32)         // 1120
#define NP   (100*OCc)           // 3000
#define QCB  80                  // Q-coop blocks: 5 w x 16 chunks of 8 ids

// ---- precomputed tables (device globals: allocation-free scratch) ----
// P layout per char (256B): [0,120): 15 x (k0lo,k0hi,k1lo,k1hi) 8B pairs
//                           [128,188): k2 pairs copy hw=0 | [192,252): copy hw=1
__device__ __half g_P4b[100*128];
__device__ float  g_Q [NQ];          // [w][id][j]
__device__ __half g_WpB[NB_*4];      // fc1 B frags
__device__ __half g_OwB[NB2_*4];     // out B frags

__device__ __forceinline__ float tanh_ap(float x) {
    float y; asm("tanh.approx.f32 %0, %1;" : "=f"(y) : "f"(x)); return y;
}
__device__ __forceinline__ void mma16816(float& c0, float& c1, float& c2, float& c3,
        uint32_t a0, uint32_t a1, uint32_t a2, uint32_t a3, uint32_t b0, uint32_t b1) {
    asm volatile("mma.sync.aligned.m16n8k16.row.col.f32.f16.f16.f32 "
        "{%0,%1,%2,%3}, {%4,%5,%6,%7}, {%8,%9}, {%0,%1,%2,%3};"
        : "+f"(c0), "+f"(c1), "+f"(c2), "+f"(c3)
        : "r"(a0), "r"(a1), "r"(a2), "r"(a3), "r"(b0), "r"(b1));
}
__device__ __forceinline__ void pair_bar(int id) {
    asm volatile("bar.sync %0, %1;" :: "r"(id), "r"(64) : "memory");
}

// one prep launch: blocks [0,QCB) compute Q cooperatively; rest: WpB | OwB | P4b
__global__ void prep_all(const float* __restrict__ conv_w,
                         const float* __restrict__ char_emb,
                         const float* __restrict__ emb,
                         const float* __restrict__ fc1_w,
                         const float* __restrict__ out_w) {
    __shared__ float sF[HIDc*WEc];
    __shared__ float sE[8*WEc];
    const int tid = threadIdx.x;

    if (blockIdx.x < QCB) {
        int w = blockIdx.x >> 4, chunk = blockIdx.x & 15;
        for (int i = tid; i < HIDc*WEc; i += 256) {
            int j = i / WEc, d = i % WEc;
            sF[i] = fc1_w[j*FCIN + w*WSTR + d];
        }
        int c0 = chunk*8;
        for (int i = tid; i < 8*WEc; i += 256)
            sE[i] = emb[(c0 + i/WEc)*WEc + (i % WEc)];
        __syncthreads();
        for (int o = tid; o < 8*HIDc; o += 256) {
            int cl = o / HIDc, j = o % HIDc;
            const float* e = &sE[cl*WEc];
            const float* f = &sF[j*WEc];
            float s = 0.f;
            #pragma unroll
            for (int d = 0; d < WEc; d++) s += e[d]*f[d];
            g_Q[(w*QN + c0 + cl)*HIDc + j] = s;
        }
        return;
    }

    int i = (blockIdx.x - QCB)*256 + tid;
    if (i < NB_) {
        int lane = i & 31, tile = i >> 5;
        int kt = tile / NTILES, nt = tile % NTILES;
        int n = nt*8 + (lane >> 2);
        int kb = kt*16 + (lane & 3)*2;
        const int koff[4] = {0, 1, 8, 9};
        __half* dst = &g_WpB[i*4];
        #pragma unroll
        for (int q = 0; q < 4; q++) {
            int k = kb + koff[q];
            float v = 0.f;
            if (k < WW*OCc && n < HIDc) {
                int w = k / OCc, oc = k % OCc;
                v = fc1_w[n*FCIN + w*WSTR + WEc + oc];
            }
            dst[q] = __float2half_rn(v);
        }
    } else if (i < NB_ + NB2_) {
        int e = i - NB_;
        int lane = e & 31, tile = e >> 5;
        int kt = tile / NT2, nt = tile % NT2;
        int n = nt*8 + (lane >> 2);
        int kb = kt*16 + (lane & 3)*2;
        const int koff[4] = {0, 1, 8, 9};
        __half* dst = &g_OwB[e*4];
        #pragma unroll
        for (int q = 0; q < 4; q++) {
            int k = kb + koff[q];
            float v = (k < HIDc && n < TAGSc) ? out_w[n*HIDc + k] : 0.f;
            dst[q] = __float2half_rn(v);
        }
    } else if (i < NB_ + NB2_ + NP) {
        int k = i - NB_ - NB2_;
        int oc = k % OCc, c = k / OCc;
        float s0 = 0.f, s1 = 0.f, s2 = 0.f;
        #pragma unroll
        for (int ce = 0; ce < CEc; ce++) {
            float e = char_emb[c*CEc + ce];
            const float* w = &conv_w[(oc*CEc + ce)*Kc];
            s0 += w[0]*e; s1 += w[1]*e; s2 += w[2]*e;
        }
        int pr = oc >> 1, lo = oc & 1;
        __half* row = &g_P4b[c*128];
        row[pr*4 + lo]      = __float2half_rn(s0);
        row[pr*4 + 2 + lo]  = __float2half_rn(s1);
        __half h2v = __float2half_rn(s2);
        row[64 + pr*2 + lo] = h2v;
        row[96 + pr*2 + lo] = h2v;
    }
}

// ---- smem layout (bytes) ----
#define OFFB_P4   0          // 25600
#define OFFB_WB   25600      // 33280
#define OFFB_WB2  58880      // 8960
#define OFFB_FB   67840      // 400
#define OFFB_OB   68240      // 160
#define OFFB_CB   68400      // 128
#define OFFB_WS   68528
// per-pair scratch: ids u16 [8*105] 1680->1696 | pool16 [8][160] 2560 | Qs f32 [8][104] 3328 | sH16 [8][112] 1792
#define PSB       9376
#define POOL_OFF  1696
#define QS_OFF    4256
#define SH_OFF    7584
#define SM_BYTES  (OFFB_WS + NPAIR*PSB + 1024)   // 219568 (+pad for benign OOB frag reads)

// fc1 mma over 8 A-rows, N-tiles [NT0, NT0+NTN)
template<int NT0, int NTN>
__device__ __forceinline__ void mma_fc1(const __half* pool16, const char* sWB,
                                        const float* Qs, __half* sH16, int lane) {
    const int lr = lane >> 2;
    const int lq = lane & 3;
    float C[NTN][4];
    #pragma unroll
    for (int t = 0; t < NTN; t++) { C[t][0]=0.f; C[t][1]=0.f; C[t][2]=0.f; C[t][3]=0.f; }
    #pragma unroll
    for (int kt = 0; kt < KTILES; kt++) {
        uint32_t a0 = *(const uint32_t*)&pool16[lr*160 + kt*16 + lq*2];
        uint32_t a2 = *(const uint32_t*)&pool16[lr*160 + kt*16 + lq*2 + 8];
        #pragma unroll
        for (int t = 0; t < NTN; t++) {
            uint2 b = *(const uint2*)(sWB + ((kt*NTILES + NT0 + t)*32 + lane)*8);
            mma16816(C[t][0], C[t][1], C[t][2], C[t][3], a0, a0, a2, a2, b.x, b.y);
        }
    }
    #pragma unroll
    for (int t = 0; t < NTN; t++) {
        int col = (NT0 + t)*8 + lq*2;
        float2 qv = *(const float2*)&Qs[lr*104 + col];
        __half2 hv = __floats2half2_rn(tanh_ap(C[t][0] + qv.x),
                                       tanh_ap(C[t][1] + qv.y));
        *(__half2*)&sH16[lr*112 + col] = hv;
    }
}

__global__ __launch_bounds__(NT) void pos_main(
    const int*   __restrict__ input,
    const float* __restrict__ emb,
    const float* __restrict__ conv_b,
    const float* __restrict__ fc1_w,
    const float* __restrict__ fc1_b,
    const float* __restrict__ out_b,
    float*       __restrict__ out,
    int nb)
{
    extern __shared__ char smb[];
    const char* sWB  = smb + OFFB_WB;
    const char* sWB2 = smb + OFFB_WB2;
    float*  sFb  = (float*)(smb + OFFB_FB);
    float*  sOb  = (float*)(smb + OFFB_OB);
    float*  sCb  = (float*)(smb + OFFB_CB);

    const int tid = threadIdx.x;

    // PDL: wait for prep_all's table writes to be visible before reading them.
    // (Blocks are pre-scheduled on the SMs while prep drains — hides launch gap.)
    cudaGridDependencySynchronize();

    // -- fill shared tables --
    {
        const int4* ps = (const int4*)g_P4b;
        int4* pd = (int4*)(smb + OFFB_P4);
        for (int i = tid; i < 1600; i += NT) pd[i] = ps[i];
        const int4* bs = (const int4*)g_WpB;
        int4* bd = (int4*)(smb + OFFB_WB);
        for (int i = tid; i < 2080; i += NT) bd[i] = bs[i];
        const int4* b2 = (const int4*)g_OwB;
        int4* bd2 = (int4*)(smb + OFFB_WB2);
        for (int i = tid; i < 560; i += NT) bd2[i] = b2[i];
        if (tid < HIDc)  sFb[tid] = fc1_b[tid];
        if (tid < TAGSc) sOb[tid] = out_b[tid];
        if (tid < OCc)   sCb[tid] = conv_b[tid];
    }
    __syncthreads();

    const int warp = tid >> 5, lane = tid & 31;
    const int pair = warp >> 1, sub = warp & 1;
    char* ws = smb + OFFB_WS + pair*PSB;
    unsigned short* sIds = (unsigned short*)ws;         // [8*105] u16
    __half* pool16 = (__half*)(ws + POOL_OFF);          // [8][160] fp16
    float*  Qs     = (float*)(ws + QS_OFF);             // [8][104] f32
    __half* sH16   = (__half*)(ws + SH_OFF);            // [8][112] fp16

    const int myb = sub*4;   // this warp owns items myb..myb+3

    // one-time pad zeroing (each warp its 4 rows)
    for (int i = lane; i < 40; i += 32)
        pool16[(myb + i/10)*160 + 150 + (i%10)] = __half(0.f);
    if (lane < 16)
        *(uint32_t*)&sH16[(myb + (lane >> 2))*112 + 104 + (lane & 3)*2] = 0u;

    // conv lane mapping: half-warp = item of pair, lane&15 = oc pair
    const int lp   = lane & 15;
    const int hw   = lane >> 4;
    const bool cact = (lp < 15);
    const char* Pk01 = smb + OFFB_P4 + lp*8;
    const char* Pk2  = smb + OFFB_P4 + 128 + hw*64 + lp*4;
    __half2 cbh = __floats2half2_rn(0.f, 0.f);
    if (cact) cbh = __floats2half2_rn(sCb[2*lp], sCb[2*lp+1]);

    const int j0 = lane*4;
    const int lr = lane >> 2, lq = lane & 3;
    const int ngroups = (nb + ITP - 1) / ITP;

    for (int group = blockIdx.x*NPAIR + pair; group < ngroups; group += gridDim.x*NPAIR) {
        const int base = group*ITP;
        const int nit = (nb - base < ITP) ? (nb - base) : ITP;
        int mynit = nit - myb; mynit = mynit < 0 ? 0 : (mynit > 4 ? 4 : mynit);

        // ids for my 4 items; char slots pre-scaled to row byte offsets (c*256)
        for (int i = lane; i < mynit*ROWI; i += 32) {
            int v = input[(base + myb)*ROWI + i];
            sIds[myb*ROWI + i] = (unsigned short)(((i % 21) == 0) ? v : (v << 8));
        }
        if (mynit < 4)
            for (int i = mynit*ROWI + lane; i < 4*ROWI; i += 32) sIds[myb*ROWI + i] = 0;
        __syncwarp();

        // -- conv + maxpool: 2 of my items/pass, half2 over oc pairs -> pool fp16 --
        if (cact) {
            #pragma unroll
            for (int ip = 0; ip < 2; ip++) {
                const int it = myb + ip*2 + hw;
                #pragma unroll 1
                for (int w = 0; w < WW; w++) {
                    const unsigned short* cc = &sIds[it*ROWI + w*21 + 1];
                    __half2 m  = __floats2half2_rn(-60000.f, -60000.f);
                    __half2 s1 = __floats2half2_rn(0.f, 0.f);
                    __half2 s0 = s1;
                    #pragma unroll
                    for (int p = 0; p < LL; p++) {
                        const int c = cc[p];
                        uint2    r01 = *(const uint2*)(Pk01 + c);
                        uint32_t r2v = *(const uint32_t*)(Pk2 + c);
                        __half2 v0 = *(const __half2*)&r01.x;
                        __half2 v1 = *(const __half2*)&r01.y;
                        __half2 v2 = *(const __half2*)&r2v;
                        if (p >= 2) m = __hmax2(m, __hadd2(s1, v2));
                        s1 = __hadd2(s0, v1);
                        s0 = v0;
                    }
                    *(__half2*)&pool16[it*160 + w*OCc + 2*lp] = __hadd2(m, cbh);
                }
            }
        }

        // -- Q phase for my 4 items --
        if (lane < 26) {
            for (int itl = 0; itl < 4; itl++) {
                const int it = myb + itl;
                float4 acc = {0.f, 0.f, 0.f, 0.f};
                if (lane < 25) {
                    if (itl < mynit) {
                        #pragma unroll
                        for (int w = 0; w < WW; w++) {
                            int id = sIds[it*ROWI + w*21];
                            if (id < QN) {
                                const float4 q = *(const float4*)&g_Q[(w*QN + id)*HIDc + j0];
                                acc.x += q.x; acc.y += q.y; acc.z += q.z; acc.w += q.w;
                            } else {   // exact fallback (never taken for this data)
                                const float* e = emb + (long)id*WEc;
                                #pragma unroll 1
                                for (int d = 0; d < WEc; d++) {
                                    float ev = e[d];
                                    acc.x += ev * fc1_w[(j0+0)*FCIN + w*WSTR + d];
                                    acc.y += ev * fc1_w[(j0+1)*FCIN + w*WSTR + d];
                                    acc.z += ev * fc1_w[(j0+2)*FCIN + w*WSTR + d];
                                    acc.w += ev * fc1_w[(j0+3)*FCIN + w*WSTR + d];
                                }
                            }
                        }
                    }
                    acc.x += sFb[j0+0]; acc.y += sFb[j0+1];
                    acc.z += sFb[j0+2]; acc.w += sFb[j0+3];
                }
                *(float4*)&Qs[it*104 + j0] = acc;
            }
        }

        pair_bar(pair);   // all 8 items' pool16 + Qs ready

        // -- fc1 on tensor cores, N-split across the warp pair --
        if (sub == 0) mma_fc1<0, 7>(pool16, sWB, Qs, sH16, lane);
        else          mma_fc1<7, 6>(pool16, sWB, Qs, sH16, lane);

        pair_bar(pair);   // sH16 complete

        // -- output layer on tensor cores, N-split: sub0 tiles 0-2, sub1 tiles 3-4 --
        {
            const int t0 = sub ? 3 : 0;
            const int tn = sub ? 2 : 3;
            float C[3][4];
            #pragma unroll
            for (int t = 0; t < 3; t++) { C[t][0]=0.f; C[t][1]=0.f; C[t][2]=0.f; C[t][3]=0.f; }
            #pragma unroll
            for (int kt = 0; kt < KT2; kt++) {
                uint32_t a0 = *(const uint32_t*)&sH16[lr*112 + kt*16 + lq*2];
                uint32_t a2 = *(const uint32_t*)&sH16[lr*112 + kt*16 + lq*2 + 8];
                #pragma unroll
                for (int t = 0; t < 3; t++) {
                    if (t < tn) {
                        uint2 b = *(const uint2*)(sWB2 + ((kt*NT2 + t0 + t)*32 + lane)*8);
                        mma16816(C[t][0], C[t][1], C[t][2], C[t][3], a0, a0, a2, a2, b.x, b.y);
                    }
                }
            }
            if (lr < nit) {
                float* orow = out + (long)(base + lr)*TAGSc;
                #pragma unroll
                for (int t = 0; t < 3; t++) {
                    if (t < tn) {
                        int c = (t0 + t)*8 + lq*2;
                        if (c < TAGSc)     orow[c]     = C[t][0] + sOb[c];
                        if (c + 1 < TAGSc) orow[c + 1] = C[t][1] + sOb[c + 1];
                    }
                }
            }
        }
        // next iteration's first pair_bar orders these reads before overwrite
    }
}

extern "C" void kernel_launch(void* const* d_in, const int* in_sizes, int n_in,
                              void* d_out, int out_size) {
    const int*   input = (const int*)  d_in[0];
    const float* emb   = (const float*)d_in[1];
    const float* cemb  = (const float*)d_in[2];
    const float* convw = (const float*)d_in[3];
    const float* convb = (const float*)d_in[4];
    const float* fc1w  = (const float*)d_in[5];
    const float* fc1b  = (const float*)d_in[6];
    const float* outw  = (const float*)d_in[7];
    const float* outb  = (const float*)d_in[8];
    float* out = (float*)d_out;

    int nb = in_sizes[0] / ROWI;

    cudaFuncSetAttribute(pos_main, cudaFuncAttributeMaxDynamicSharedMemorySize, SM_BYTES);

    int tail_blocks = (NB_ + NB2_ + NP + 255)/256;     // 33
    prep_all<<<QCB + tail_blocks, 256>>>(convw, cemb, emb, fc1w, outw);

    // PDL launch: pos_main pre-launches while prep_all drains; the in-kernel
    // cudaGridDependencySynchronize() provides the data dependency.
    cudaLaunchAttribute attrs[1];
    attrs[0].id = cudaLaunchAttributeProgrammaticStreamSerialization;
    attrs[0].val.programmaticStreamSerializationAllowed = 1;
    cudaLaunchConfig_t cfg = {};
    cfg.gridDim = dim3(148);
    cfg.blockDim = dim3(NT);
    cfg.dynamicSmemBytes = SM_BYTES;
    cfg.stream = 0;
    cfg.attrs = attrs;
    cfg.numAttrs = 1;
    cudaLaunchKernelEx(&cfg, pos_main,
                       input, emb, convb, fc1w, fc1b, outb, out, nb);
}